// round 5
// baseline (speedup 1.0000x reference)
#include <cuda_runtime.h>
#include <cuda_bf16.h>

// Problem constants
#define PW 32
#define PL 64
#define PK 512
#define PN 64
#define ROWS_PER_W (PL * PK)            // 32768
#define TOTAL_ROWS (PW * ROWS_PER_W)    // 1048576
#define EN_ELEMS   TOTAL_ROWS
#define MASK_ELEMS (PW * (PL - 1) * PK) // 1032192

// Scratch (no allocs allowed -> __device__ globals)
__device__ unsigned char       g_mask[MASK_ELEMS];
__device__ unsigned long long  g_packed[TOTAL_ROWS];   // 8 MB: states rows as 64-bit masks

#define QT_STRIDE  72   // halves; padded -> conflict-free column reads
#define A_STRIDE   72   // halves; 144B row stride -> conflict-free LDSM

__device__ __forceinline__ unsigned pack_bf16(float lo, float hi) {
    __nv_bfloat162 h = __floats2bfloat162_rn(lo, hi);
    return *reinterpret_cast<unsigned*>(&h);
}

__device__ __forceinline__ void mma_bf16(float* d, const unsigned* a, unsigned b0, unsigned b1) {
    asm volatile(
        "mma.sync.aligned.m16n8k16.row.col.f32.bf16.bf16.f32 "
        "{%0,%1,%2,%3}, {%4,%5,%6,%7}, {%8,%9}, {%0,%1,%2,%3};"
        : "+f"(d[0]), "+f"(d[1]), "+f"(d[2]), "+f"(d[3])
        : "r"(a[0]), "r"(a[1]), "r"(a[2]), "r"(a[3]), "r"(b0), "r"(b1));
}

__device__ __forceinline__ void ldsm_x4(unsigned* r, const __nv_bfloat16* p) {
    unsigned a = (unsigned)__cvta_generic_to_shared(p);
    asm volatile("ldmatrix.sync.aligned.m8n8.x4.shared.b16 {%0,%1,%2,%3}, [%4];"
                 : "=r"(r[0]), "=r"(r[1]), "=r"(r[2]), "=r"(r[3]) : "r"(a));
}

__device__ __forceinline__ void barg(int id) {
    asm volatile("bar.sync %0, 128;" :: "r"(id) : "memory");
}

// ---------------------------------------------------------------------------
// Kernel 1: energies via bf16-split MMA, warp-specialized over N.
//   CTA = 256 threads = 2 groups x 4 warps. Within a group, warp q owns
//   N-tiles {2q, 2q+1} and holds their B fragments (3 splits) in registers
//   for the entire kernel. A (16 rows x 64) is staged to smem as bf16 and
//   read by all 4 warps via ldmatrix. Partial energies + 16-bit state chunks
//   are combined across warps through smem (double buffered).
// ---------------------------------------------------------------------------
__global__ void __launch_bounds__(256, 2)
energies_kernel(const float* __restrict__ states,
                const float* __restrict__ Qg,
                float* __restrict__ energies_out) {
    const int w   = blockIdx.y;    // 0..31
    const int cta = blockIdx.x;    // 0..63
    const int tid = threadIdx.x;

    __shared__ __nv_bfloat16 sQT[3][PN * QT_STRIDE];            // 27.6 KB
    __shared__ __nv_bfloat16 sA[2][2][16 * A_STRIDE];           // 9.2 KB [group][parity]
    __shared__ float         sPart[2][2][4][16];                // 1 KB
    __shared__ unsigned      sBits[2][2][4][16];                // 1 KB

    // Build Q^T splits in smem
    const float* Qw = Qg + (size_t)w * PN * PN;
    for (int idx = tid; idx < PN * PN; idx += 256) {
        const int i = idx >> 6;
        const int j = idx & 63;
        float q = Qw[idx];
        __nv_bfloat16 h = __float2bfloat16(q);
        float r = q - __bfloat162float(h);
        __nv_bfloat16 m = __float2bfloat16(r);
        float r2 = r - __bfloat162float(m);
        __nv_bfloat16 lo = __float2bfloat16(r2);
        sQT[0][j * QT_STRIDE + i] = h;
        sQT[1][j * QT_STRIDE + i] = m;
        sQT[2][j * QT_STRIDE + i] = lo;
    }
    __syncthreads();

    const int warp = tid >> 5;
    const int lane = tid & 31;
    const int grp  = warp >> 2;   // 0,1
    const int q    = warp & 3;    // warp-in-group: owns nt = {2q, 2q+1}
    const int g    = lane >> 2;   // 0..7
    const int tg   = lane & 3;    // 0..3

    // B fragments to registers (once): Bf[sp][kc][ntl][2]
    unsigned Bf[3][4][2][2];
    #pragma unroll
    for (int sp = 0; sp < 3; sp++)
        #pragma unroll
        for (int kc = 0; kc < 4; kc++)
            #pragma unroll
            for (int ntl = 0; ntl < 2; ntl++) {
                const int n = (2 * q + ntl) * 8 + g;
                const __nv_bfloat16* p = sQT[sp] + n * QT_STRIDE + kc * 16 + tg * 2;
                Bf[sp][kc][ntl][0] = *reinterpret_cast<const unsigned*>(p);
                Bf[sp][kc][ntl][1] = *reinterpret_cast<const unsigned*>(p + 8);
            }

    const int group_row_base = w * ROWS_PER_W + cta * 512 + grp * 256;
    const int gtid  = tid & 127;         // thread id within group
    const int srow  = gtid >> 3;         // 0..15
    const int scol  = (gtid & 7) * 8;    // 0,8,...,56

    // ldmatrix lane address components (fixed per lane)
    const int mmat = lane >> 3;                 // matrix id 0..3
    const int mrow = (lane & 7) + ((mmat & 1) ? 8 : 0);
    const int mcol = (mmat & 2) ? 8 : 0;
    __nv_bfloat16* sAg0 = &sA[grp][0][mrow * A_STRIDE + mcol];
    __nv_bfloat16* sAg1 = &sA[grp][1][mrow * A_STRIDE + mcol];

    #pragma unroll 1
    for (int t = 0; t < 16; t++) {
        const int par = t & 1;
        const int rb  = group_row_base + t * 16;

        // Stage A: 16x64 f32 -> bf16x2 -> smem (each thread: 8 floats)
        {
            const float4* src = reinterpret_cast<const float4*>(
                states + (size_t)(rb + srow) * PN + scol);
            float4 v0 = src[0];
            float4 v1 = src[1];
            uint4 pk;
            pk.x = pack_bf16(v0.x, v0.y);
            pk.y = pack_bf16(v0.z, v0.w);
            pk.z = pack_bf16(v1.x, v1.y);
            pk.w = pack_bf16(v1.z, v1.w);
            *reinterpret_cast<uint4*>(&sA[grp][par][srow * A_STRIDE + scol]) = pk;
        }
        barg(1 + grp);

        // A fragments via ldmatrix
        unsigned af[4][4];
        {
            __nv_bfloat16* base = par ? sAg1 : sAg0;
            #pragma unroll
            for (int kc = 0; kc < 4; kc++)
                ldsm_x4(af[kc], base + kc * 16);
        }

        // MMAs: 3 splits x 4 kc x 2 owned N-tiles
        float d[2][4];
        #pragma unroll
        for (int ntl = 0; ntl < 2; ntl++)
            #pragma unroll
            for (int e = 0; e < 4; e++) d[ntl][e] = 0.0f;

        #pragma unroll
        for (int sp = 0; sp < 3; sp++)
            #pragma unroll
            for (int kc = 0; kc < 4; kc++) {
                mma_bf16(d[0], af[kc], Bf[sp][kc][0][0], Bf[sp][kc][0][1]);
                mma_bf16(d[1], af[kc], Bf[sp][kc][1][0], Bf[sp][kc][1][1]);
            }

        // Partial epilogue over this warp's 16 j-columns (cols q*16..q*16+15).
        // s bits for those columns live in af[q]:
        //   af[q][0]: rows g,  cols q*16+2tg,+1    -> d[0][0], d[0][1]
        //   af[q][1]: rows g+8, same cols          -> d[0][2], d[0][3]
        //   af[q][2]: rows g,  cols q*16+2tg+8,+9  -> d[1][0], d[1][1]
        //   af[q][3]: rows g+8, same cols          -> d[1][2], d[1][3]
        float eg = 0.0f, eg8 = 0.0f;
        unsigned cg = 0u, cg8 = 0u;
        {
            unsigned a;
            a = af[q][0];
            if (a & 0xFFFFu) { eg  += d[0][0]; cg  |= 1u << (2 * tg); }
            if (a >> 16)     { eg  += d[0][1]; cg  |= 1u << (2 * tg + 1); }
            a = af[q][1];
            if (a & 0xFFFFu) { eg8 += d[0][2]; cg8 |= 1u << (2 * tg); }
            if (a >> 16)     { eg8 += d[0][3]; cg8 |= 1u << (2 * tg + 1); }
            a = af[q][2];
            if (a & 0xFFFFu) { eg  += d[1][0]; cg  |= 1u << (2 * tg + 8); }
            if (a >> 16)     { eg  += d[1][1]; cg  |= 1u << (2 * tg + 9); }
            a = af[q][3];
            if (a & 0xFFFFu) { eg8 += d[1][2]; cg8 |= 1u << (2 * tg + 8); }
            if (a >> 16)     { eg8 += d[1][3]; cg8 |= 1u << (2 * tg + 9); }
        }
        eg  += __shfl_xor_sync(0xffffffffu, eg, 1);
        eg  += __shfl_xor_sync(0xffffffffu, eg, 2);
        eg8 += __shfl_xor_sync(0xffffffffu, eg8, 1);
        eg8 += __shfl_xor_sync(0xffffffffu, eg8, 2);
        cg  |= __shfl_xor_sync(0xffffffffu, cg, 1);
        cg  |= __shfl_xor_sync(0xffffffffu, cg, 2);
        cg8 |= __shfl_xor_sync(0xffffffffu, cg8, 1);
        cg8 |= __shfl_xor_sync(0xffffffffu, cg8, 2);
        if (tg == 0) {
            sPart[grp][par][q][g]     = eg;
            sPart[grp][par][q][8 + g] = eg8;
            sBits[grp][par][q][g]     = cg;
            sBits[grp][par][q][8 + g] = cg8;
        }
        barg(1 + grp);

        // Warp 0 of the group finalizes 16 rows
        if (q == 0 && lane < 16) {
            const int row = rb + lane;
            float e = sPart[grp][par][0][lane] + sPart[grp][par][1][lane]
                    + sPart[grp][par][2][lane] + sPart[grp][par][3][lane];
            energies_out[row] = e;
            unsigned long long p =
                  (unsigned long long)(sBits[grp][par][0][lane] & 0xFFFFu)
                | ((unsigned long long)(sBits[grp][par][1][lane] & 0xFFFFu) << 16)
                | ((unsigned long long)(sBits[grp][par][2][lane] & 0xFFFFu) << 32)
                | ((unsigned long long)(sBits[grp][par][3][lane] & 0xFFFFu) << 48);
            g_packed[row] = p;
        }
    }
}

// ---------------------------------------------------------------------------
// Kernel 2: mask[w,j,k] = u < exp((E[j+1]-E[j]) * (beta[j+1]-beta[j]))
// ---------------------------------------------------------------------------
__global__ void __launch_bounds__(256)
mask_kernel(const float* __restrict__ energies,
            const float* __restrict__ beta,
            const float* __restrict__ u) {
    const int idx = blockIdx.x * 256 + threadIdx.x;
    const int k = idx & 511;
    const int j = (idx >> 9) % 63;
    const int w = idx / (63 * 512);
    const float e1 = energies[(w * PL + j) * PK + k];
    const float e2 = energies[(w * PL + j + 1) * PK + k];
    const float db = beta[j + 1] - beta[j];
    const float delta = (e2 - e1) * db;
    g_mask[idx] = (u[idx] < expf(delta)) ? 1 : 0;
}

// ---------------------------------------------------------------------------
// Kernel 3: row-gather swap from PACKED bits (reads 9 MB instead of 268 MB).
//   out[w,0]   = mask[w,0]   ? states[w,1]   : states[w,0]
//   out[w,l>0] = mask[w,l-1] ? states[w,l-1] : states[w,l]
// ---------------------------------------------------------------------------
__global__ void __launch_bounds__(256)
swap_kernel(float* __restrict__ out_states) {
    const int tid  = blockIdx.x * 256 + threadIdx.x;  // < TOTAL_ROWS * 4
    const int part = tid & 3;
    const int row  = tid >> 2;
    const int k = row & 511;
    const int l = (row >> 9) & 63;
    const int w = row >> 15;

    const int j = (l == 0) ? 0 : (l - 1);
    const bool m = g_mask[(w * 63 + j) * PK + k] != 0;
    int src;
    if (l == 0) src = m ? 1 : 0;
    else        src = m ? (l - 1) : l;

    const int src_row = (w * PL + src) * PK + k;
    const unsigned bits = (unsigned)(g_packed[src_row] >> (part * 16)) & 0xFFFFu;

    float4* dst = reinterpret_cast<float4*>(out_states + (((size_t)row) << 6) + (part << 4));
    #pragma unroll
    for (int qq = 0; qq < 4; qq++) {
        float4 v;
        v.x = (bits >> (qq * 4 + 0)) & 1u ? 1.0f : 0.0f;
        v.y = (bits >> (qq * 4 + 1)) & 1u ? 1.0f : 0.0f;
        v.z = (bits >> (qq * 4 + 2)) & 1u ? 1.0f : 0.0f;
        v.w = (bits >> (qq * 4 + 3)) & 1u ? 1.0f : 0.0f;
        dst[qq] = v;
    }
}

// ---------------------------------------------------------------------------

extern "C" void kernel_launch(void* const* d_in, const int* in_sizes, int n_in,
                              void* d_out, int out_size) {
    const float* states = (const float*)d_in[0];  // (32,64,512,64) f32
    const float* Q      = (const float*)d_in[1];  // (32,64,64) f32
    const float* beta   = (const float*)d_in[2];  // (64,) f32
    const float* u      = (const float*)d_in[3];  // (32,63,512) f32

    float* energies   = (float*)d_out;
    float* out_states = (float*)d_out + EN_ELEMS;

    dim3 egrid(64, PW);
    energies_kernel<<<egrid, 256>>>(states, Q, energies);

    mask_kernel<<<MASK_ELEMS / 256, 256>>>(energies, beta, u);

    swap_kernel<<<(TOTAL_ROWS * 4) / 256, 256>>>(out_states);
}

// round 6
// speedup vs baseline: 1.3558x; 1.3558x over previous
#include <cuda_runtime.h>
#include <cuda_bf16.h>

// Problem constants
#define PW 32
#define PL 64
#define PK 512
#define PN 64
#define ROWS_PER_W (PL * PK)            // 32768
#define TOTAL_ROWS (PW * ROWS_PER_W)    // 1048576
#define EN_ELEMS   TOTAL_ROWS
#define MASK_ELEMS (PW * (PL - 1) * PK) // 1032192

// Scratch (no allocs allowed -> __device__ globals)
__device__ unsigned char       g_mask[MASK_ELEMS];
__device__ unsigned long long  g_packed[TOTAL_ROWS];   // 8 MB: states rows as 64-bit masks

#define QT_STRIDE 72  // halves; padded -> conflict-free column reads

__device__ __forceinline__ unsigned pack_bf16(float lo, float hi) {
    __nv_bfloat162 h = __floats2bfloat162_rn(lo, hi);
    return *reinterpret_cast<unsigned*>(&h);
}

__device__ __forceinline__ void mma_bf16(float* d, const unsigned* a, unsigned b0, unsigned b1) {
    asm volatile(
        "mma.sync.aligned.m16n8k16.row.col.f32.bf16.bf16.f32 "
        "{%0,%1,%2,%3}, {%4,%5,%6,%7}, {%8,%9}, {%0,%1,%2,%3};"
        : "+f"(d[0]), "+f"(d[1]), "+f"(d[2]), "+f"(d[3])
        : "r"(a[0]), "r"(a[1]), "r"(a[2]), "r"(a[3]), "r"(b0), "r"(b1));
}

// ---------------------------------------------------------------------------
// Kernel 1: energies via bf16-split MMA, nt-outer / fold-early accumulation.
//   Warp owns 64 rows (4 blocks of 16). For each N-tile (8 j-columns):
//   zero 4-reg accumulators per block, run 3 splits x 4 k-chunks of MMAs
//   (B fragments loaded ONCE per nt and shared by all 4 blocks), then fold
//   d into scalar energies using the s bits already in the A fragments.
//   B LDS traffic: 192 loads per 64 rows (4x less than R3). No barriers.
// ---------------------------------------------------------------------------
__global__ void __launch_bounds__(256, 2)
energies_kernel(const float* __restrict__ states,
                const float* __restrict__ Qg,
                float* __restrict__ energies_out) {
    const int w   = blockIdx.y;    // 0..31
    const int cta = blockIdx.x;    // 0..63
    const int tid = threadIdx.x;

    __shared__ __nv_bfloat16 sQT[3][PN * QT_STRIDE];

    // Build Q^T splits in smem (Q = hi + mid + lo, ~24 mantissa bits)
    const float* Qw = Qg + (size_t)w * PN * PN;
    for (int idx = tid; idx < PN * PN; idx += 256) {
        const int i = idx >> 6;
        const int j = idx & 63;
        float q = Qw[idx];
        __nv_bfloat16 h = __float2bfloat16(q);
        float r = q - __bfloat162float(h);
        __nv_bfloat16 m = __float2bfloat16(r);
        float r2 = r - __bfloat162float(m);
        __nv_bfloat16 lo = __float2bfloat16(r2);
        sQT[0][j * QT_STRIDE + i] = h;
        sQT[1][j * QT_STRIDE + i] = m;
        sQT[2][j * QT_STRIDE + i] = lo;
    }
    __syncthreads();

    const int warp = tid >> 5;
    const int lane = tid & 31;
    const int g  = lane >> 2;  // 0..7
    const int tg = lane & 3;   // 0..3

    const int row_base = w * ROWS_PER_W + cta * 512 + warp * 64;

    // A fragments for 4 blocks of 16 rows (64 regs), loaded upfront (high MLP)
    unsigned af[4][4][4];
    #pragma unroll
    for (int bi = 0; bi < 4; bi++) {
        const float* rowg  = states + (size_t)(row_base + bi * 16 + g) * PN;
        const float* rowg8 = rowg + 8 * PN;
        #pragma unroll
        for (int kc = 0; kc < 4; kc++) {
            const int c0 = kc * 16 + tg * 2;
            float2 v;
            v = *reinterpret_cast<const float2*>(rowg  + c0);     af[bi][kc][0] = pack_bf16(v.x, v.y);
            v = *reinterpret_cast<const float2*>(rowg8 + c0);     af[bi][kc][1] = pack_bf16(v.x, v.y);
            v = *reinterpret_cast<const float2*>(rowg  + c0 + 8); af[bi][kc][2] = pack_bf16(v.x, v.y);
            v = *reinterpret_cast<const float2*>(rowg8 + c0 + 8); af[bi][kc][3] = pack_bf16(v.x, v.y);
        }
    }

    float eg[4]  = {0.f, 0.f, 0.f, 0.f};
    float eg8[4] = {0.f, 0.f, 0.f, 0.f};

    // bf16(1.0) = 0x3F80 -> bit 7 (low half) / bit 23 (high half) test the s bit
    #pragma unroll
    for (int nt = 0; nt < 8; nt++) {
        const int kc0 = nt >> 1;
        const int rlo = (nt & 1) ? 2 : 0;
        const int rhi = (nt & 1) ? 3 : 1;

        float d[4][4];
        #pragma unroll
        for (int bi = 0; bi < 4; bi++)
            #pragma unroll
            for (int e = 0; e < 4; e++) d[bi][e] = 0.0f;

        const int n = nt * 8 + g;
        #pragma unroll
        for (int sp = 0; sp < 3; sp++) {
            const __nv_bfloat16* qt = sQT[sp] + n * QT_STRIDE + tg * 2;
            unsigned b0[4], b1[4];
            #pragma unroll
            for (int kc = 0; kc < 4; kc++) {
                b0[kc] = *reinterpret_cast<const unsigned*>(qt + kc * 16);
                b1[kc] = *reinterpret_cast<const unsigned*>(qt + kc * 16 + 8);
            }
            #pragma unroll
            for (int kc = 0; kc < 4; kc++)
                #pragma unroll
                for (int bi = 0; bi < 4; bi++)
                    mma_bf16(d[bi], af[bi][kc], b0[kc], b1[kc]);
        }

        // Fold this nt's 8 j-columns into the scalar energies.
        // Lane owns j = nt*8 + 2tg, +1 for rows g (d[0],d[1]) and g+8 (d[2],d[3]);
        // the matching s bits live in af[bi][kc0][rlo] / af[bi][kc0][rhi].
        #pragma unroll
        for (int bi = 0; bi < 4; bi++) {
            unsigned a = af[bi][kc0][rlo];
            if (a & 0x80u)     eg[bi]  += d[bi][0];
            if (a & 0x800000u) eg[bi]  += d[bi][1];
            a = af[bi][kc0][rhi];
            if (a & 0x80u)     eg8[bi] += d[bi][2];
            if (a & 0x800000u) eg8[bi] += d[bi][3];
        }
    }

    // Epilogue: reduce over tg, pack state bits, store.
    #pragma unroll
    for (int bi = 0; bi < 4; bi++) {
        float e0 = eg[bi], e8 = eg8[bi];
        e0 += __shfl_xor_sync(0xffffffffu, e0, 1);
        e0 += __shfl_xor_sync(0xffffffffu, e0, 2);
        e8 += __shfl_xor_sync(0xffffffffu, e8, 1);
        e8 += __shfl_xor_sync(0xffffffffu, e8, 2);

        // Pack the 64 s bits of rows (g) and (g+8) from the bf16 fragments.
        // Column of af[bi][kc] regs {0,2}: 16kc+2tg{,+1,+8,+9} (row g), regs {1,3} row g+8.
        unsigned plo = 0, phi = 0, qlo = 0, qhi = 0;
        #pragma unroll
        for (int kc = 0; kc < 4; kc++) {
            const unsigned a0 = af[bi][kc][0], a1 = af[bi][kc][1];
            const unsigned a2 = af[bi][kc][2], a3 = af[bi][kc][3];
            unsigned m0 = ((a0 >> 7) & 1u) | ((a0 >> 22) & 2u)
                        | (((a2 >> 7) & 1u) << 8) | (((a2 >> 22) & 2u) << 8);
            unsigned m8 = ((a1 >> 7) & 1u) | ((a1 >> 22) & 2u)
                        | (((a3 >> 7) & 1u) << 8) | (((a3 >> 22) & 2u) << 8);
            const int sh = (kc & 1) * 16 + tg * 2;
            if (kc < 2) { plo |= m0 << sh; qlo |= m8 << sh; }
            else        { phi |= m0 << sh; qhi |= m8 << sh; }
        }
        plo |= __shfl_xor_sync(0xffffffffu, plo, 1);
        plo |= __shfl_xor_sync(0xffffffffu, plo, 2);
        phi |= __shfl_xor_sync(0xffffffffu, phi, 1);
        phi |= __shfl_xor_sync(0xffffffffu, phi, 2);
        qlo |= __shfl_xor_sync(0xffffffffu, qlo, 1);
        qlo |= __shfl_xor_sync(0xffffffffu, qlo, 2);
        qhi |= __shfl_xor_sync(0xffffffffu, qhi, 1);
        qhi |= __shfl_xor_sync(0xffffffffu, qhi, 2);

        if (tg == 0) {
            const int r0 = row_base + bi * 16 + g;
            energies_out[r0]     = e0;
            energies_out[r0 + 8] = e8;
            reinterpret_cast<uint2*>(g_packed)[r0]     = make_uint2(plo, phi);
            reinterpret_cast<uint2*>(g_packed)[r0 + 8] = make_uint2(qlo, qhi);
        }
    }
}

// ---------------------------------------------------------------------------
// Kernel 2: mask[w,j,k] = u < exp((E[j+1]-E[j]) * (beta[j+1]-beta[j]))
// ---------------------------------------------------------------------------
__global__ void __launch_bounds__(256)
mask_kernel(const float* __restrict__ energies,
            const float* __restrict__ beta,
            const float* __restrict__ u) {
    const int idx = blockIdx.x * 256 + threadIdx.x;
    const int k = idx & 511;
    const int j = (idx >> 9) % 63;
    const int w = idx / (63 * 512);
    const float e1 = energies[(w * PL + j) * PK + k];
    const float e2 = energies[(w * PL + j + 1) * PK + k];
    const float db = beta[j + 1] - beta[j];
    const float delta = (e2 - e1) * db;
    g_mask[idx] = (u[idx] < expf(delta)) ? 1 : 0;
}

// ---------------------------------------------------------------------------
// Kernel 3: row-gather swap from PACKED bits (reads 9 MB instead of 268 MB).
//   out[w,0]   = mask[w,0]   ? states[w,1]   : states[w,0]
//   out[w,l>0] = mask[w,l-1] ? states[w,l-1] : states[w,l]
// ---------------------------------------------------------------------------
__global__ void __launch_bounds__(256)
swap_kernel(float* __restrict__ out_states) {
    const int tid  = blockIdx.x * 256 + threadIdx.x;  // < TOTAL_ROWS * 4
    const int part = tid & 3;
    const int row  = tid >> 2;
    const int k = row & 511;
    const int l = (row >> 9) & 63;
    const int w = row >> 15;

    const int j = (l == 0) ? 0 : (l - 1);
    const bool m = g_mask[(w * 63 + j) * PK + k] != 0;
    int src;
    if (l == 0) src = m ? 1 : 0;
    else        src = m ? (l - 1) : l;

    const int src_row = (w * PL + src) * PK + k;
    const unsigned bits = (unsigned)(g_packed[src_row] >> (part * 16)) & 0xFFFFu;

    float4* dst = reinterpret_cast<float4*>(out_states + (((size_t)row) << 6) + (part << 4));
    #pragma unroll
    for (int qq = 0; qq < 4; qq++) {
        float4 v;
        v.x = (bits >> (qq * 4 + 0)) & 1u ? 1.0f : 0.0f;
        v.y = (bits >> (qq * 4 + 1)) & 1u ? 1.0f : 0.0f;
        v.z = (bits >> (qq * 4 + 2)) & 1u ? 1.0f : 0.0f;
        v.w = (bits >> (qq * 4 + 3)) & 1u ? 1.0f : 0.0f;
        __stcs(dst + qq, v);   // streaming store: output is never re-read
    }
}

// ---------------------------------------------------------------------------

extern "C" void kernel_launch(void* const* d_in, const int* in_sizes, int n_in,
                              void* d_out, int out_size) {
    const float* states = (const float*)d_in[0];  // (32,64,512,64) f32
    const float* Q      = (const float*)d_in[1];  // (32,64,64) f32
    const float* beta   = (const float*)d_in[2];  // (64,) f32
    const float* u      = (const float*)d_in[3];  // (32,63,512) f32

    float* energies   = (float*)d_out;
    float* out_states = (float*)d_out + EN_ELEMS;

    dim3 egrid(64, PW);
    energies_kernel<<<egrid, 256>>>(states, Q, energies);

    mask_kernel<<<MASK_ELEMS / 256, 256>>>(energies, beta, u);

    swap_kernel<<<(TOTAL_ROWS * 4) / 256, 256>>>(out_states);
}